// round 6
// baseline (speedup 1.0000x reference)
#include <cuda_runtime.h>

#define NN   50000
#define EE   800000
#define ETOT 850000   // E + N self loops
#define F1   128      // HEADS*HID
#define H    4
#define FOUT 32

// ---------------- scratch (device globals; no allocations allowed) ----------
__device__ __align__(16) float g_h1[NN * F1];      // layer1 transformed features
__device__ __align__(16) float g_out1[NN * F1];    // layer1 aggregate (pre-ELU)
__device__ __align__(16) float g_als1[NN * H];
__device__ __align__(16) float g_ald1[NN * H];
__device__ __align__(16) float g_dinv1[NN * H];    // 1/denom
__device__ __align__(16) float g_e1[(size_t)ETOT * H];   // p (sorted edge order)
__device__ __align__(16) float g_h2[NN * FOUT];
__device__ __align__(16) float g_als2[NN];
__device__ __align__(16) float g_ald2[NN];
__device__ __align__(16) float g_dinv2[NN];
__device__ __align__(16) float g_e2[ETOT];
__device__ int g_src[ETOT];
__device__ int g_dst[ETOT];
__device__ int g_cnt[NN];
__device__ int g_cursor[NN];
__device__ int g_rowptr[NN + 1];
__device__ int g_ssrc[ETOT];        // src ids sorted by dst
__device__ int g_is64;

// ---------------- helpers ---------------------------------------------------
__device__ __forceinline__ float lrelu(float v) { return v > 0.f ? v : 0.2f * v; }

// ---------------- edge dtype detection + decode ------------------------------
__global__ void k_detect(const int* __restrict__ ei32) {
    __shared__ int any_nonzero;
    if (threadIdx.x == 0) any_nonzero = 0;
    __syncthreads();
    if (ei32[2 * (threadIdx.x * 1237) + 1] != 0) atomicOr(&any_nonzero, 1);
    __syncthreads();
    if (threadIdx.x == 0) g_is64 = any_nonzero ? 0 : 1;
}

__global__ void k_decode(const void* __restrict__ ei) {
    int i = blockIdx.x * blockDim.x + threadIdx.x;
    if (i >= ETOT) return;
    int s, d;
    if (i >= EE) {
        s = d = i - EE;                     // self loop
    } else if (g_is64) {
        const long long* p = (const long long*)ei;
        s = (int)p[i]; d = (int)p[EE + i];
    } else {
        const int* q = (const int*)ei;
        s = q[i]; d = q[EE + i];
    }
    if ((unsigned)s >= NN) s = 0;
    if ((unsigned)d >= NN) d = 0;
    g_src[i] = s;
    g_dst[i] = d;
}

// ---------------- counting sort by dst ---------------------------------------
__global__ void k_zero() {
    int i = blockIdx.x * blockDim.x + threadIdx.x;
    if (i < NN) g_cnt[i] = 0;
}

__global__ void k_hist() {
    int i = blockIdx.x * blockDim.x + threadIdx.x;
    if (i < ETOT) atomicAdd(&g_cnt[g_dst[i]], 1);
}

// single block, 1024 threads: exclusive prefix sum of g_cnt -> g_rowptr/g_cursor
__global__ void k_scan() {
    __shared__ int part[1024];
    int tid = threadIdx.x;
    const int CH = (NN + 1023) / 1024;   // 49
    int lo = tid * CH, hi = lo + CH;
    if (hi > NN) hi = NN;
    int s = 0;
    for (int i = lo; i < hi; i++) s += g_cnt[i];
    part[tid] = s;
    __syncthreads();
    for (int off = 1; off < 1024; off <<= 1) {
        int v = (tid >= off) ? part[tid - off] : 0;
        __syncthreads();
        part[tid] += v;
        __syncthreads();
    }
    int run = (tid == 0) ? 0 : part[tid - 1];
    for (int i = lo; i < hi; i++) {
        g_rowptr[i] = run;
        g_cursor[i] = run;
        run += g_cnt[i];
    }
    if (tid == 1023) g_rowptr[NN] = ETOT;
}

__global__ void k_scatter() {
    int i = blockIdx.x * blockDim.x + threadIdx.x;
    if (i >= ETOT) return;
    int d = g_dst[i];
    int pos = atomicAdd(&g_cursor[d], 1);
    g_ssrc[pos] = g_src[i];
}

// ---------------- GEMM1: h1 = x @ W1  (50000x128 @ 128x128) ------------------
// R3 version (measured 50.1us): 64-node tile, 8x4 micro-tile.
__global__ void k_gemm1(const float* __restrict__ x, const float* __restrict__ W) {
    __shared__ float Ws[64 * 128];   // [kk][c]
    __shared__ float Xs[64 * 64];    // [m][kk]
    int tid = threadIdx.x;
    int tx = tid & 31;               // col group: c0 = tx*4
    int ty = tid >> 5;               // node group: m0 = ty*8
    int bm = blockIdx.x * 64;

    float acc[8][4];
#pragma unroll
    for (int i = 0; i < 8; i++)
#pragma unroll
        for (int j = 0; j < 4; j++) acc[i][j] = 0.f;

    for (int kt = 0; kt < 2; kt++) {
        const float4* Wg = (const float4*)(W + kt * 64 * 128);
        float4* Ws4 = (float4*)Ws;
#pragma unroll
        for (int r = 0; r < 8; r++) Ws4[tid + r * 256] = Wg[tid + r * 256];
        float4* Xs4 = (float4*)Xs;
#pragma unroll
        for (int r = 0; r < 4; r++) {
            int v = tid + r * 256;        // float4 index, 16 per row
            int m = v >> 4, kv = v & 15;
            int node = bm + m;
            float4 val = make_float4(0.f, 0.f, 0.f, 0.f);
            if (node < NN)
                val = *(const float4*)(x + (size_t)node * 128 + kt * 64 + kv * 4);
            Xs4[v] = val;
        }
        __syncthreads();
#pragma unroll 8
        for (int kk = 0; kk < 64; kk++) {
            float4 w = ((const float4*)Ws)[kk * 32 + tx];
#pragma unroll
            for (int i = 0; i < 8; i++) {
                float xv = Xs[(ty * 8 + i) * 64 + kk];
                acc[i][0] += xv * w.x;
                acc[i][1] += xv * w.y;
                acc[i][2] += xv * w.z;
                acc[i][3] += xv * w.w;
            }
        }
        __syncthreads();
    }
#pragma unroll
    for (int i = 0; i < 8; i++) {
        int node = bm + ty * 8 + i;
        if (node < NN)
            *(float4*)(g_h1 + (size_t)node * 128 + tx * 4) =
                make_float4(acc[i][0], acc[i][1], acc[i][2], acc[i][3]);
    }
}

// ---------------- attention scalars layer1 ----------------------------------
__global__ void k_al1(const float* __restrict__ a_src, const float* __restrict__ a_dst) {
    int i = blockIdx.x * blockDim.x + threadIdx.x;
    if (i >= NN * H) return;
    int n = i >> 2, h = i & 3;
    const float* hp = g_h1 + (size_t)n * 128 + h * 32;
    float s = 0.f, d = 0.f;
#pragma unroll
    for (int j = 0; j < 8; j++) {
        float4 v  = *(const float4*)(hp + j * 4);
        float4 as = *(const float4*)(a_src + h * 32 + j * 4);
        float4 ad = *(const float4*)(a_dst + h * 32 + j * 4);
        s += v.x * as.x + v.y * as.y + v.z * as.z + v.w * as.w;
        d += v.x * ad.x + v.y * ad.y + v.z * ad.z + v.w * ad.w;
    }
    g_als1[i] = s;
    g_ald1[i] = d;
}

// ---------------- layer1 softmax: warp per node, lane per edge ---------------
__global__ void k_soft1() {
    int w = (blockIdx.x * blockDim.x + threadIdx.x) >> 5;
    int lane = threadIdx.x & 31;
    if (w >= NN) return;
    int beg = g_rowptr[w], end = g_rowptr[w + 1];
    float4 ad = *(const float4*)(g_ald1 + w * 4);
    float4 sum = make_float4(0.f, 0.f, 0.f, 0.f);
    for (int e = beg + lane; e < end; e += 32) {
        int s = g_ssrc[e];
        float4 as = *(const float4*)(g_als1 + s * 4);
        float4 p;
        p.x = __expf(lrelu(as.x + ad.x));
        p.y = __expf(lrelu(as.y + ad.y));
        p.z = __expf(lrelu(as.z + ad.z));
        p.w = __expf(lrelu(as.w + ad.w));
        *(float4*)(g_e1 + (size_t)e * 4) = p;
        sum.x += p.x; sum.y += p.y; sum.z += p.z; sum.w += p.w;
    }
#pragma unroll
    for (int off = 16; off; off >>= 1) {
        sum.x += __shfl_down_sync(0xffffffffu, sum.x, off);
        sum.y += __shfl_down_sync(0xffffffffu, sum.y, off);
        sum.z += __shfl_down_sync(0xffffffffu, sum.z, off);
        sum.w += __shfl_down_sync(0xffffffffu, sum.w, off);
    }
    if (lane == 0) {
        float4 inv;
        inv.x = 1.f / fmaxf(sum.x, 1e-16f);
        inv.y = 1.f / fmaxf(sum.y, 1e-16f);
        inv.z = 1.f / fmaxf(sum.z, 1e-16f);
        inv.w = 1.f / fmaxf(sum.w, 1e-16f);
        *(float4*)(g_dinv1 + w * 4) = inv;
    }
}

// ---------------- layer1 aggregate: warp per node, no atomics ----------------
__global__ void k_agg1(const float* __restrict__ b1) {
    int w = (blockIdx.x * blockDim.x + threadIdx.x) >> 5;
    int lane = threadIdx.x & 31;
    if (w >= NN) return;
    int beg = g_rowptr[w], end = g_rowptr[w + 1];
    int head = lane >> 3;
    float dinv = g_dinv1[w * 4 + head];
    float4 acc = *(const float4*)(b1 + lane * 4);
    for (int e = beg; e < end; e++) {
        int s = g_ssrc[e];
        float alpha = g_e1[(size_t)e * 4 + head] * dinv;
        float4 v = *(const float4*)(g_h1 + (size_t)s * 128 + lane * 4);
        acc.x += alpha * v.x;
        acc.y += alpha * v.y;
        acc.z += alpha * v.z;
        acc.w += alpha * v.w;
    }
    *(float4*)(g_out1 + (size_t)w * 128 + lane * 4) = acc;
}

// ---------------- GEMM2 (ELU fused on load): h2 = elu(out1) @ W2 -------------
__global__ void k_gemm2(const float* __restrict__ W) {
    __shared__ float Ws[128 * 32];   // [k][c]
    __shared__ float Xs[64 * 128];   // [m][k]
    int tid = threadIdx.x;
    int tx = tid & 31;               // col
    int ty = tid >> 5;               // node group of 8
    int bm = blockIdx.x * 64;

    float4* Ws4 = (float4*)Ws;
    const float4* Wg = (const float4*)W;
#pragma unroll
    for (int r = 0; r < 4; r++) Ws4[tid + r * 256] = Wg[tid + r * 256];

    float4* Xs4 = (float4*)Xs;
#pragma unroll
    for (int r = 0; r < 8; r++) {
        int v = tid + r * 256;       // float4 index; 32 per row
        int m = v >> 5, kv = v & 31;
        int node = bm + m;
        float4 val = make_float4(0.f, 0.f, 0.f, 0.f);
        if (node < NN) {
            val = *(const float4*)(g_out1 + (size_t)node * 128 + kv * 4);
            val.x = val.x > 0.f ? val.x : __expf(val.x) - 1.f;
            val.y = val.y > 0.f ? val.y : __expf(val.y) - 1.f;
            val.z = val.z > 0.f ? val.z : __expf(val.z) - 1.f;
            val.w = val.w > 0.f ? val.w : __expf(val.w) - 1.f;
        }
        Xs4[v] = val;
    }
    __syncthreads();

    float acc[8];
#pragma unroll
    for (int i = 0; i < 8; i++) acc[i] = 0.f;
#pragma unroll 8
    for (int k = 0; k < 128; k++) {
        float w = Ws[k * 32 + tx];
#pragma unroll
        for (int i = 0; i < 8; i++) acc[i] += Xs[(ty * 8 + i) * 128 + k] * w;
    }
#pragma unroll
    for (int i = 0; i < 8; i++) {
        int node = bm + ty * 8 + i;
        if (node < NN) g_h2[(size_t)node * 32 + tx] = acc[i];
    }
}

// ---------------- attention scalars layer2 ----------------------------------
__global__ void k_al2(const float* __restrict__ a_src, const float* __restrict__ a_dst) {
    int n = blockIdx.x * blockDim.x + threadIdx.x;
    if (n >= NN) return;
    const float* hp = g_h2 + (size_t)n * 32;
    float s = 0.f, d = 0.f;
#pragma unroll
    for (int j = 0; j < 8; j++) {
        float4 v  = *(const float4*)(hp + j * 4);
        float4 as = *(const float4*)(a_src + j * 4);
        float4 ad = *(const float4*)(a_dst + j * 4);
        s += v.x * as.x + v.y * as.y + v.z * as.z + v.w * as.w;
        d += v.x * ad.x + v.y * ad.y + v.z * ad.z + v.w * ad.w;
    }
    g_als2[n] = s;
    g_ald2[n] = d;
}

// ---------------- layer2 softmax: warp per node ------------------------------
__global__ void k_soft2() {
    int w = (blockIdx.x * blockDim.x + threadIdx.x) >> 5;
    int lane = threadIdx.x & 31;
    if (w >= NN) return;
    int beg = g_rowptr[w], end = g_rowptr[w + 1];
    float adn = g_ald2[w];
    float sum = 0.f;
    for (int e = beg + lane; e < end; e += 32) {
        int s = g_ssrc[e];
        float p = __expf(lrelu(g_als2[s] + adn));
        g_e2[e] = p;
        sum += p;
    }
#pragma unroll
    for (int off = 16; off; off >>= 1)
        sum += __shfl_down_sync(0xffffffffu, sum, off);
    if (lane == 0) g_dinv2[w] = 1.f / fmaxf(sum, 1e-16f);
}

// ---------------- layer2 aggregate: warp per node, lane per channel ----------
__global__ void k_agg2(const float* __restrict__ b2, float* __restrict__ out) {
    int w = (blockIdx.x * blockDim.x + threadIdx.x) >> 5;
    int lane = threadIdx.x & 31;
    if (w >= NN) return;
    int beg = g_rowptr[w], end = g_rowptr[w + 1];
    float dinv = g_dinv2[w];
    float acc = b2[lane];
    for (int e = beg; e < end; e++) {
        int s = g_ssrc[e];
        float alpha = g_e2[e] * dinv;
        acc += alpha * g_h2[(size_t)s * 32 + lane];
    }
    out[(size_t)w * 32 + lane] = acc;
}

// ---------------- launcher ---------------------------------------------------
extern "C" void kernel_launch(void* const* d_in, const int* in_sizes, int n_in,
                              void* d_out, int out_size) {
    const float* x      = (const float*)d_in[0];
    const float* W1     = (const float*)d_in[1];
    const float* a_src1 = (const float*)d_in[2];
    const float* a_dst1 = (const float*)d_in[3];
    const float* b1     = (const float*)d_in[4];
    const float* W2     = (const float*)d_in[5];
    const float* a_src2 = (const float*)d_in[6];
    const float* a_dst2 = (const float*)d_in[7];
    const float* b2     = (const float*)d_in[8];
    const void*  ei     = (const void*)d_in[9];
    float* out = (float*)d_out;

    k_detect <<<1, 256>>>((const int*)ei);
    k_decode <<<(ETOT + 255) / 256, 256>>>(ei);
    k_zero   <<<(NN + 255) / 256, 256>>>();
    k_hist   <<<(ETOT + 255) / 256, 256>>>();
    k_scan   <<<1, 1024>>>();
    k_scatter<<<(ETOT + 255) / 256, 256>>>();
    k_gemm1  <<<(NN + 63) / 64, 256>>>(x, W1);
    k_al1    <<<(NN * H + 255) / 256, 256>>>(a_src1, a_dst1);
    k_soft1  <<<(NN * 32 + 255) / 256, 256>>>();
    k_agg1   <<<(NN * 32 + 255) / 256, 256>>>(b1);
    k_gemm2  <<<(NN + 63) / 64, 256>>>(W2);
    k_al2    <<<(NN + 255) / 256, 256>>>(a_src2, a_dst2);
    k_soft2  <<<(NN * 32 + 255) / 256, 256>>>();
    k_agg2   <<<(NN * 32 + 255) / 256, 256>>>(b2, out);
}

// round 8
// speedup vs baseline: 1.4899x; 1.4899x over previous
#include <cuda_runtime.h>
#include <cstdint>

#define NN   50000
#define EE   800000
#define ETOT 850000   // E + N self loops
#define F1   128      // HEADS*HID
#define H    4
#define FOUT 32
#define NB   196      // ceil(NN/256)

// ---------------- scratch (device globals; no allocations allowed) ----------
__device__ __align__(16) float g_h1[NN * F1];
__device__ __align__(16) float g_out1[NN * F1];
__device__ __align__(16) float g_als1[NN * H];
__device__ __align__(16) float g_ald1[NN * H];
__device__ __align__(16) float g_dinv1[NN * H];
__device__ __align__(16) float g_e1[(size_t)ETOT * H];
__device__ __align__(16) float g_h2[NN * FOUT];
__device__ __align__(16) float g_als2[NN];
__device__ __align__(16) float g_ald2[NN];
__device__ __align__(16) float g_dinv2[NN];
__device__ __align__(16) float g_e2[ETOT];
__device__ int g_src[ETOT];
__device__ int g_dst[ETOT];
__device__ int g_cnt[NN];
__device__ int g_cursor[NN];
__device__ int g_rowptr[NN + 1];
__device__ int g_ssrc[ETOT];
__device__ int g_bsum[NB];
__device__ int g_boff[NB];
__device__ int g_is64;

// ---------------- helpers ---------------------------------------------------
__device__ __forceinline__ float lrelu(float v) { return v > 0.f ? v : 0.2f * v; }
__device__ __forceinline__ uint32_t f2tf(float f) {
    uint32_t u; asm("cvt.rna.tf32.f32 %0, %1;" : "=r"(u) : "f"(f)); return u;
}

// ---------------- edge dtype detection ---------------------------------------
__global__ void k_detect(const int* __restrict__ ei32) {
    __shared__ int any_nonzero;
    if (threadIdx.x == 0) any_nonzero = 0;
    __syncthreads();
    if (ei32[2 * (threadIdx.x * 1237) + 1] != 0) atomicOr(&any_nonzero, 1);
    __syncthreads();
    if (threadIdx.x == 0) g_is64 = any_nonzero ? 0 : 1;
}

__global__ void k_zero() {
    int i = blockIdx.x * blockDim.x + threadIdx.x;
    if (i < NN) g_cnt[i] = 0;
}

// decode + histogram fused
__global__ void k_decode(const void* __restrict__ ei) {
    int i = blockIdx.x * blockDim.x + threadIdx.x;
    if (i >= ETOT) return;
    int s, d;
    if (i >= EE) {
        s = d = i - EE;
    } else if (g_is64) {
        const long long* p = (const long long*)ei;
        s = (int)p[i]; d = (int)p[EE + i];
    } else {
        const int* q = (const int*)ei;
        s = q[i]; d = q[EE + i];
    }
    if ((unsigned)s >= NN) s = 0;
    if ((unsigned)d >= NN) d = 0;
    g_src[i] = s;
    g_dst[i] = d;
    atomicAdd(&g_cnt[d], 1);
}

// ---------------- parallel 3-stage exclusive scan of g_cnt -------------------
__global__ void k_scanA() {
    int b = blockIdx.x, tid = threadIdx.x;
    int i = b * 256 + tid;
    int c = (i < NN) ? g_cnt[i] : 0;
    int lane = tid & 31, wid = tid >> 5;
#pragma unroll
    for (int off = 16; off; off >>= 1) c += __shfl_down_sync(0xffffffffu, c, off);
    __shared__ int ws[8];
    if (lane == 0) ws[wid] = c;
    __syncthreads();
    if (tid == 0) {
        int s = 0;
#pragma unroll
        for (int j = 0; j < 8; j++) s += ws[j];
        g_bsum[b] = s;
    }
}

__global__ void k_scanB() {   // 1 block, 256 threads
    int tid = threadIdx.x;
    __shared__ int sh[256];
    int v = (tid < NB) ? g_bsum[tid] : 0;
    sh[tid] = v;
    __syncthreads();
    for (int off = 1; off < 256; off <<= 1) {
        int n = (tid >= off) ? sh[tid - off] : 0;
        __syncthreads();
        sh[tid] += n;
        __syncthreads();
    }
    if (tid < NB) g_boff[tid] = sh[tid] - v;   // exclusive
}

__global__ void k_scanC() {
    int b = blockIdx.x, tid = threadIdx.x;
    int i = b * 256 + tid;
    int c = (i < NN) ? g_cnt[i] : 0;
    int lane = tid & 31, wid = tid >> 5;
    int v = c;
#pragma unroll
    for (int off = 1; off < 32; off <<= 1) {
        int n = __shfl_up_sync(0xffffffffu, v, off);
        if (lane >= off) v += n;
    }
    __shared__ int ws[8];
    if (lane == 31) ws[wid] = v;
    __syncthreads();
    if (wid == 0) {
        int s = (lane < 8) ? ws[lane] : 0;
#pragma unroll
        for (int off = 1; off < 8; off <<= 1) {
            int n = __shfl_up_sync(0xffffffffu, s, off);
            if (lane >= off) s += n;
        }
        if (lane < 8) ws[lane] = s;
    }
    __syncthreads();
    int excl = v - c + (wid ? ws[wid - 1] : 0) + g_boff[b];
    if (i < NN) { g_rowptr[i] = excl; g_cursor[i] = excl; }
    if (i == 0) g_rowptr[NN] = ETOT;
}

__global__ void k_scatter() {
    int i = blockIdx.x * blockDim.x + threadIdx.x;
    if (i >= ETOT) return;
    int d = g_dst[i];
    int pos = atomicAdd(&g_cursor[d], 1);
    g_ssrc[pos] = g_src[i];
}

// ---------------- GEMM1 (tf32 tensor cores): h1 = x @ W1 ---------------------
// block: 256 thr (8 warps); tile M=128, N=128; warp = 16 rows x 128 cols.
// K chunked by 16 (2 mma k-steps per chunk); W chunk staged in smem (tf32),
// row stride 136 words -> conflict-free B-fragment LDS.
__global__ __launch_bounds__(256) void k_gemm1(const float* __restrict__ x,
                                               const float* __restrict__ W) {
    __shared__ uint32_t Ws[16 * 136];
    int tid  = threadIdx.x;
    int w    = tid >> 5;
    int lane = tid & 31;
    int g    = lane >> 2;
    int t    = lane & 3;
    int bm   = blockIdx.x * 128;

    int row0 = bm + w * 16 + g;
    int row1 = row0 + 8;
    bool ok0 = row0 < NN, ok1 = row1 < NN;
    const float* xr0 = x + (size_t)(ok0 ? row0 : 0) * 128;
    const float* xr1 = x + (size_t)(ok1 ? row1 : 0) * 128;

    float acc[16][4];
#pragma unroll
    for (int n = 0; n < 16; n++)
#pragma unroll
        for (int j = 0; j < 4; j++) acc[n][j] = 0.f;

    for (int chunk = 0; chunk < 8; chunk++) {
        // stage W rows chunk*16..+16 (128 cols) as tf32
        const float4* Wg = (const float4*)(W + chunk * 16 * 128);
#pragma unroll
        for (int r = 0; r < 2; r++) {
            int idx = tid + r * 256;          // 512 float4 total
            int row = idx >> 5, cv = idx & 31;
            float4 wv = Wg[row * 32 + cv];
            uint4 tv = make_uint4(f2tf(wv.x), f2tf(wv.y), f2tf(wv.z), f2tf(wv.w));
            *(uint4*)(Ws + row * 136 + cv * 4) = tv;
        }
        __syncthreads();
#pragma unroll
        for (int ks = 0; ks < 2; ks++) {
            int k0 = chunk * 16 + ks * 8;
            int kk = ks * 8;
            uint32_t a0 = ok0 ? f2tf(xr0[k0 + t])     : 0u;
            uint32_t a2 = ok0 ? f2tf(xr0[k0 + t + 4]) : 0u;
            uint32_t a1 = ok1 ? f2tf(xr1[k0 + t])     : 0u;
            uint32_t a3 = ok1 ? f2tf(xr1[k0 + t + 4]) : 0u;
#pragma unroll
            for (int n = 0; n < 16; n++) {
                uint32_t b0 = Ws[(kk + t) * 136 + n * 8 + g];
                uint32_t b1 = Ws[(kk + t + 4) * 136 + n * 8 + g];
                asm volatile(
                    "mma.sync.aligned.m16n8k8.row.col.f32.tf32.tf32.f32 "
                    "{%0,%1,%2,%3}, {%4,%5,%6,%7}, {%8,%9}, {%0,%1,%2,%3};"
                    : "+f"(acc[n][0]), "+f"(acc[n][1]), "+f"(acc[n][2]), "+f"(acc[n][3])
                    : "r"(a0), "r"(a1), "r"(a2), "r"(a3), "r"(b0), "r"(b1));
            }
        }
        __syncthreads();
    }
#pragma unroll
    for (int n = 0; n < 16; n++) {
        if (ok0) *(float2*)(g_h1 + (size_t)row0 * 128 + n * 8 + 2 * t) =
            make_float2(acc[n][0], acc[n][1]);
        if (ok1) *(float2*)(g_h1 + (size_t)row1 * 128 + n * 8 + 2 * t) =
            make_float2(acc[n][2], acc[n][3]);
    }
}

// ---------------- attention scalars layer1 ----------------------------------
__global__ void k_al1(const float* __restrict__ a_src, const float* __restrict__ a_dst) {
    int i = blockIdx.x * blockDim.x + threadIdx.x;
    if (i >= NN * H) return;
    int n = i >> 2, h = i & 3;
    const float* hp = g_h1 + (size_t)n * 128 + h * 32;
    float s = 0.f, d = 0.f;
#pragma unroll
    for (int j = 0; j < 8; j++) {
        float4 v  = *(const float4*)(hp + j * 4);
        float4 as = *(const float4*)(a_src + h * 32 + j * 4);
        float4 ad = *(const float4*)(a_dst + h * 32 + j * 4);
        s += v.x * as.x + v.y * as.y + v.z * as.z + v.w * as.w;
        d += v.x * ad.x + v.y * ad.y + v.z * ad.z + v.w * ad.w;
    }
    g_als1[i] = s;
    g_ald1[i] = d;
}

// ---------------- layer1 softmax: warp per node ------------------------------
__global__ void k_soft1() {
    int w = (blockIdx.x * blockDim.x + threadIdx.x) >> 5;
    int lane = threadIdx.x & 31;
    if (w >= NN) return;
    int beg = g_rowptr[w], end = g_rowptr[w + 1];
    float4 ad = *(const float4*)(g_ald1 + w * 4);
    float4 sum = make_float4(0.f, 0.f, 0.f, 0.f);
    for (int e = beg + lane; e < end; e += 32) {
        int s = g_ssrc[e];
        float4 as = *(const float4*)(g_als1 + s * 4);
        float4 p;
        p.x = __expf(lrelu(as.x + ad.x));
        p.y = __expf(lrelu(as.y + ad.y));
        p.z = __expf(lrelu(as.z + ad.z));
        p.w = __expf(lrelu(as.w + ad.w));
        *(float4*)(g_e1 + (size_t)e * 4) = p;
        sum.x += p.x; sum.y += p.y; sum.z += p.z; sum.w += p.w;
    }
#pragma unroll
    for (int off = 16; off; off >>= 1) {
        sum.x += __shfl_down_sync(0xffffffffu, sum.x, off);
        sum.y += __shfl_down_sync(0xffffffffu, sum.y, off);
        sum.z += __shfl_down_sync(0xffffffffu, sum.z, off);
        sum.w += __shfl_down_sync(0xffffffffu, sum.w, off);
    }
    if (lane == 0) {
        float4 inv;
        inv.x = 1.f / fmaxf(sum.x, 1e-16f);
        inv.y = 1.f / fmaxf(sum.y, 1e-16f);
        inv.z = 1.f / fmaxf(sum.z, 1e-16f);
        inv.w = 1.f / fmaxf(sum.w, 1e-16f);
        *(float4*)(g_dinv1 + w * 4) = inv;
    }
}

// ---------------- layer1 aggregate: warp per node, unroll x2 -----------------
__global__ void k_agg1(const float* __restrict__ b1) {
    int w = (blockIdx.x * blockDim.x + threadIdx.x) >> 5;
    int lane = threadIdx.x & 31;
    if (w >= NN) return;
    int beg = g_rowptr[w], end = g_rowptr[w + 1];
    int head = lane >> 3;
    float dinv = g_dinv1[w * 4 + head];
    float4 acc = *(const float4*)(b1 + lane * 4);
    int e = beg;
    for (; e + 2 <= end; e += 2) {
        int s0 = g_ssrc[e], s1 = g_ssrc[e + 1];
        float al0 = g_e1[(size_t)e * 4 + head];
        float al1 = g_e1[(size_t)(e + 1) * 4 + head];
        float4 v0 = *(const float4*)(g_h1 + (size_t)s0 * 128 + lane * 4);
        float4 v1 = *(const float4*)(g_h1 + (size_t)s1 * 128 + lane * 4);
        al0 *= dinv; al1 *= dinv;
        acc.x += al0 * v0.x + al1 * v1.x;
        acc.y += al0 * v0.y + al1 * v1.y;
        acc.z += al0 * v0.z + al1 * v1.z;
        acc.w += al0 * v0.w + al1 * v1.w;
    }
    if (e < end) {
        int s0 = g_ssrc[e];
        float al0 = g_e1[(size_t)e * 4 + head] * dinv;
        float4 v0 = *(const float4*)(g_h1 + (size_t)s0 * 128 + lane * 4);
        acc.x += al0 * v0.x; acc.y += al0 * v0.y;
        acc.z += al0 * v0.z; acc.w += al0 * v0.w;
    }
    *(float4*)(g_out1 + (size_t)w * 128 + lane * 4) = acc;
}

// ---------------- GEMM2 (ELU fused on load): h2 = elu(out1) @ W2 -------------
__global__ void k_gemm2(const float* __restrict__ W) {
    __shared__ float Ws[128 * 32];
    __shared__ float Xs[64 * 128];
    int tid = threadIdx.x;
    int tx = tid & 31;
    int ty = tid >> 5;
    int bm = blockIdx.x * 64;

    float4* Ws4 = (float4*)Ws;
    const float4* Wg = (const float4*)W;
#pragma unroll
    for (int r = 0; r < 4; r++) Ws4[tid + r * 256] = Wg[tid + r * 256];

    float4* Xs4 = (float4*)Xs;
#pragma unroll
    for (int r = 0; r < 8; r++) {
        int v = tid + r * 256;
        int m = v >> 5, kv = v & 31;
        int node = bm + m;
        float4 val = make_float4(0.f, 0.f, 0.f, 0.f);
        if (node < NN) {
            val = *(const float4*)(g_out1 + (size_t)node * 128 + kv * 4);
            val.x = val.x > 0.f ? val.x : __expf(val.x) - 1.f;
            val.y = val.y > 0.f ? val.y : __expf(val.y) - 1.f;
            val.z = val.z > 0.f ? val.z : __expf(val.z) - 1.f;
            val.w = val.w > 0.f ? val.w : __expf(val.w) - 1.f;
        }
        Xs4[v] = val;
    }
    __syncthreads();

    float acc[8];
#pragma unroll
    for (int i = 0; i < 8; i++) acc[i] = 0.f;
#pragma unroll 8
    for (int k = 0; k < 128; k++) {
        float w = Ws[k * 32 + tx];
#pragma unroll
        for (int i = 0; i < 8; i++) acc[i] += Xs[(ty * 8 + i) * 128 + k] * w;
    }
#pragma unroll
    for (int i = 0; i < 8; i++) {
        int node = bm + ty * 8 + i;
        if (node < NN) g_h2[(size_t)node * 32 + tx] = acc[i];
    }
}

// ---------------- attention scalars layer2 ----------------------------------
__global__ void k_al2(const float* __restrict__ a_src, const float* __restrict__ a_dst) {
    int n = blockIdx.x * blockDim.x + threadIdx.x;
    if (n >= NN) return;
    const float* hp = g_h2 + (size_t)n * 32;
    float s = 0.f, d = 0.f;
#pragma unroll
    for (int j = 0; j < 8; j++) {
        float4 v  = *(const float4*)(hp + j * 4);
        float4 as = *(const float4*)(a_src + j * 4);
        float4 ad = *(const float4*)(a_dst + j * 4);
        s += v.x * as.x + v.y * as.y + v.z * as.z + v.w * as.w;
        d += v.x * ad.x + v.y * ad.y + v.z * ad.z + v.w * ad.w;
    }
    g_als2[n] = s;
    g_ald2[n] = d;
}

// ---------------- layer2 softmax: warp per node ------------------------------
__global__ void k_soft2() {
    int w = (blockIdx.x * blockDim.x + threadIdx.x) >> 5;
    int lane = threadIdx.x & 31;
    if (w >= NN) return;
    int beg = g_rowptr[w], end = g_rowptr[w + 1];
    float adn = g_ald2[w];
    float sum = 0.f;
    for (int e = beg + lane; e < end; e += 32) {
        int s = g_ssrc[e];
        float p = __expf(lrelu(g_als2[s] + adn));
        g_e2[e] = p;
        sum += p;
    }
#pragma unroll
    for (int off = 16; off; off >>= 1)
        sum += __shfl_down_sync(0xffffffffu, sum, off);
    if (lane == 0) g_dinv2[w] = 1.f / fmaxf(sum, 1e-16f);
}

// ---------------- layer2 aggregate: warp per node, unroll x2 -----------------
__global__ void k_agg2(const float* __restrict__ b2, float* __restrict__ out) {
    int w = (blockIdx.x * blockDim.x + threadIdx.x) >> 5;
    int lane = threadIdx.x & 31;
    if (w >= NN) return;
    int beg = g_rowptr[w], end = g_rowptr[w + 1];
    float dinv = g_dinv2[w];
    float acc = b2[lane];
    int e = beg;
    for (; e + 2 <= end; e += 2) {
        int s0 = g_ssrc[e], s1 = g_ssrc[e + 1];
        float al0 = g_e2[e], al1 = g_e2[e + 1];
        float v0 = g_h2[(size_t)s0 * 32 + lane];
        float v1 = g_h2[(size_t)s1 * 32 + lane];
        acc += al0 * dinv * v0 + al1 * dinv * v1;
    }
    if (e < end) {
        int s0 = g_ssrc[e];
        acc += g_e2[e] * dinv * g_h2[(size_t)s0 * 32 + lane];
    }
    out[(size_t)w * 32 + lane] = acc;
}

// ---------------- launcher ---------------------------------------------------
extern "C" void kernel_launch(void* const* d_in, const int* in_sizes, int n_in,
                              void* d_out, int out_size) {
    const float* x      = (const float*)d_in[0];
    const float* W1     = (const float*)d_in[1];
    const float* a_src1 = (const float*)d_in[2];
    const float* a_dst1 = (const float*)d_in[3];
    const float* b1     = (const float*)d_in[4];
    const float* W2     = (const float*)d_in[5];
    const float* a_src2 = (const float*)d_in[6];
    const float* a_dst2 = (const float*)d_in[7];
    const float* b2     = (const float*)d_in[8];
    const void*  ei     = (const void*)d_in[9];
    float* out = (float*)d_out;

    k_detect <<<1, 256>>>((const int*)ei);
    k_zero   <<<NB, 256>>>();
    k_decode <<<(ETOT + 255) / 256, 256>>>(ei);
    k_scanA  <<<NB, 256>>>();
    k_scanB  <<<1, 256>>>();
    k_scanC  <<<NB, 256>>>();
    k_scatter<<<(ETOT + 255) / 256, 256>>>();
    k_gemm1  <<<(NN + 127) / 128, 256>>>(x, W1);
    k_al1    <<<(NN * H + 255) / 256, 256>>>(a_src1, a_dst1);
    k_soft1  <<<(NN * 32 + 255) / 256, 256>>>();
    k_agg1   <<<(NN * 32 + 255) / 256, 256>>>(b1);
    k_gemm2  <<<(NN + 63) / 64, 256>>>(W2);
    k_al2    <<<(NN + 255) / 256, 256>>>(a_src2, a_dst2);
    k_soft2  <<<(NN * 32 + 255) / 256, 256>>>();
    k_agg2   <<<(NN * 32 + 255) / 256, 256>>>(b2, out);
}

// round 9
// speedup vs baseline: 1.6140x; 1.0833x over previous
#include <cuda_runtime.h>
#include <cstdint>

#define NN   50000
#define EE   800000
#define ETOT 850000   // E + N self loops
#define F1   128      // HEADS*HID
#define H    4
#define FOUT 32
#define NB   196      // ceil(NN/256)

// ---------------- scratch (device globals; no allocations allowed) ----------
__device__ __align__(16) float g_h1[NN * F1];
__device__ __align__(16) float g_out1[NN * F1];
__device__ __align__(16) float g_als1[NN * H];
__device__ __align__(16) float g_ald1[NN * H];
__device__ __align__(16) float g_h2[NN * FOUT];
__device__ __align__(16) float g_als2[NN];
__device__ __align__(16) float g_ald2[NN];
__device__ int g_src[ETOT];
__device__ int g_dst[ETOT];
__device__ int g_cnt[NN];
__device__ int g_cursor[NN];
__device__ int g_rowptr[NN + 1];
__device__ int g_ssrc[ETOT];
__device__ int g_bsum[NB];
__device__ int g_boff[NB];
__device__ int g_is64;

// ---------------- helpers ---------------------------------------------------
__device__ __forceinline__ float lrelu(float v) { return v > 0.f ? v : 0.2f * v; }
__device__ __forceinline__ uint32_t f2tf(float f) {
    uint32_t u; asm("cvt.rna.tf32.f32 %0, %1;" : "=r"(u) : "f"(f)); return u;
}
__device__ __forceinline__ float eluf(float v) {
    return v > 0.f ? v : __expf(v) - 1.f;
}

// ---------------- edge dtype detection ---------------------------------------
__global__ void k_detect(const int* __restrict__ ei32) {
    __shared__ int any_nonzero;
    if (threadIdx.x == 0) any_nonzero = 0;
    __syncthreads();
    if (ei32[2 * (threadIdx.x * 1237) + 1] != 0) atomicOr(&any_nonzero, 1);
    __syncthreads();
    if (threadIdx.x == 0) g_is64 = any_nonzero ? 0 : 1;
}

__global__ void k_zero() {
    int i = blockIdx.x * blockDim.x + threadIdx.x;
    if (i < NN) g_cnt[i] = 0;
}

// decode + histogram fused
__global__ void k_decode(const void* __restrict__ ei) {
    int i = blockIdx.x * blockDim.x + threadIdx.x;
    if (i >= ETOT) return;
    int s, d;
    if (i >= EE) {
        s = d = i - EE;
    } else if (g_is64) {
        const long long* p = (const long long*)ei;
        s = (int)p[i]; d = (int)p[EE + i];
    } else {
        const int* q = (const int*)ei;
        s = q[i]; d = q[EE + i];
    }
    if ((unsigned)s >= NN) s = 0;
    if ((unsigned)d >= NN) d = 0;
    g_src[i] = s;
    g_dst[i] = d;
    atomicAdd(&g_cnt[d], 1);
}

// ---------------- parallel 3-stage exclusive scan of g_cnt -------------------
__global__ void k_scanA() {
    int b = blockIdx.x, tid = threadIdx.x;
    int i = b * 256 + tid;
    int c = (i < NN) ? g_cnt[i] : 0;
    int lane = tid & 31, wid = tid >> 5;
#pragma unroll
    for (int off = 16; off; off >>= 1) c += __shfl_down_sync(0xffffffffu, c, off);
    __shared__ int ws[8];
    if (lane == 0) ws[wid] = c;
    __syncthreads();
    if (tid == 0) {
        int s = 0;
#pragma unroll
        for (int j = 0; j < 8; j++) s += ws[j];
        g_bsum[b] = s;
    }
}

__global__ void k_scanB() {   // 1 block, 256 threads
    int tid = threadIdx.x;
    __shared__ int sh[256];
    int v = (tid < NB) ? g_bsum[tid] : 0;
    sh[tid] = v;
    __syncthreads();
    for (int off = 1; off < 256; off <<= 1) {
        int n = (tid >= off) ? sh[tid - off] : 0;
        __syncthreads();
        sh[tid] += n;
        __syncthreads();
    }
    if (tid < NB) g_boff[tid] = sh[tid] - v;   // exclusive
}

__global__ void k_scanC() {
    int b = blockIdx.x, tid = threadIdx.x;
    int i = b * 256 + tid;
    int c = (i < NN) ? g_cnt[i] : 0;
    int lane = tid & 31, wid = tid >> 5;
    int v = c;
#pragma unroll
    for (int off = 1; off < 32; off <<= 1) {
        int n = __shfl_up_sync(0xffffffffu, v, off);
        if (lane >= off) v += n;
    }
    __shared__ int ws[8];
    if (lane == 31) ws[wid] = v;
    __syncthreads();
    if (wid == 0) {
        int s = (lane < 8) ? ws[lane] : 0;
#pragma unroll
        for (int off = 1; off < 8; off <<= 1) {
            int n = __shfl_up_sync(0xffffffffu, s, off);
            if (lane >= off) s += n;
        }
        if (lane < 8) ws[lane] = s;
    }
    __syncthreads();
    int excl = v - c + (wid ? ws[wid - 1] : 0) + g_boff[b];
    if (i < NN) { g_rowptr[i] = excl; g_cursor[i] = excl; }
    if (i == 0) g_rowptr[NN] = ETOT;
}

__global__ void k_scatter() {
    int i = blockIdx.x * blockDim.x + threadIdx.x;
    if (i >= ETOT) return;
    int d = g_dst[i];
    int pos = atomicAdd(&g_cursor[d], 1);
    g_ssrc[pos] = g_src[i];
}

// ---------------- GEMM1 (tf32 tensor cores): h1 = x @ W1 ---------------------
__global__ __launch_bounds__(256) void k_gemm1(const float* __restrict__ x,
                                               const float* __restrict__ W) {
    __shared__ uint32_t Ws[16 * 136];
    int tid  = threadIdx.x;
    int w    = tid >> 5;
    int lane = tid & 31;
    int g    = lane >> 2;
    int t    = lane & 3;
    int bm   = blockIdx.x * 128;

    int row0 = bm + w * 16 + g;
    int row1 = row0 + 8;
    bool ok0 = row0 < NN, ok1 = row1 < NN;
    const float* xr0 = x + (size_t)(ok0 ? row0 : 0) * 128;
    const float* xr1 = x + (size_t)(ok1 ? row1 : 0) * 128;

    float acc[16][4];
#pragma unroll
    for (int n = 0; n < 16; n++)
#pragma unroll
        for (int j = 0; j < 4; j++) acc[n][j] = 0.f;

    for (int chunk = 0; chunk < 8; chunk++) {
        const float4* Wg = (const float4*)(W + chunk * 16 * 128);
#pragma unroll
        for (int r = 0; r < 2; r++) {
            int idx = tid + r * 256;
            int row = idx >> 5, cv = idx & 31;
            float4 wv = Wg[row * 32 + cv];
            uint4 tv = make_uint4(f2tf(wv.x), f2tf(wv.y), f2tf(wv.z), f2tf(wv.w));
            *(uint4*)(Ws + row * 136 + cv * 4) = tv;
        }
        __syncthreads();
#pragma unroll
        for (int ks = 0; ks < 2; ks++) {
            int k0 = chunk * 16 + ks * 8;
            int kk = ks * 8;
            uint32_t a0 = ok0 ? f2tf(xr0[k0 + t])     : 0u;
            uint32_t a2 = ok0 ? f2tf(xr0[k0 + t + 4]) : 0u;
            uint32_t a1 = ok1 ? f2tf(xr1[k0 + t])     : 0u;
            uint32_t a3 = ok1 ? f2tf(xr1[k0 + t + 4]) : 0u;
#pragma unroll
            for (int n = 0; n < 16; n++) {
                uint32_t b0 = Ws[(kk + t) * 136 + n * 8 + g];
                uint32_t b1 = Ws[(kk + t + 4) * 136 + n * 8 + g];
                asm volatile(
                    "mma.sync.aligned.m16n8k8.row.col.f32.tf32.tf32.f32 "
                    "{%0,%1,%2,%3}, {%4,%5,%6,%7}, {%8,%9}, {%0,%1,%2,%3};"
                    : "+f"(acc[n][0]), "+f"(acc[n][1]), "+f"(acc[n][2]), "+f"(acc[n][3])
                    : "r"(a0), "r"(a1), "r"(a2), "r"(a3), "r"(b0), "r"(b1));
            }
        }
        __syncthreads();
    }
#pragma unroll
    for (int n = 0; n < 16; n++) {
        if (ok0) *(float2*)(g_h1 + (size_t)row0 * 128 + n * 8 + 2 * t) =
            make_float2(acc[n][0], acc[n][1]);
        if (ok1) *(float2*)(g_h1 + (size_t)row1 * 128 + n * 8 + 2 * t) =
            make_float2(acc[n][2], acc[n][3]);
    }
}

// ---------------- attention scalars layer1 ----------------------------------
__global__ void k_al1(const float* __restrict__ a_src, const float* __restrict__ a_dst) {
    int i = blockIdx.x * blockDim.x + threadIdx.x;
    if (i >= NN * H) return;
    int n = i >> 2, h = i & 3;
    const float* hp = g_h1 + (size_t)n * 128 + h * 32;
    float s = 0.f, d = 0.f;
#pragma unroll
    for (int j = 0; j < 8; j++) {
        float4 v  = *(const float4*)(hp + j * 4);
        float4 as = *(const float4*)(a_src + h * 32 + j * 4);
        float4 ad = *(const float4*)(a_dst + h * 32 + j * 4);
        s += v.x * as.x + v.y * as.y + v.z * as.z + v.w * as.w;
        d += v.x * ad.x + v.y * ad.y + v.z * ad.z + v.w * ad.w;
    }
    g_als1[i] = s;
    g_ald1[i] = d;
}

// ---------------- layer1 fused softmax+aggregate: warp per node --------------
// out = (Σ_e p_e * h1[src_e]) / (Σ_e p_e) + b1, p_e = exp(lrelu(als+ald))
__global__ void k_fagg1(const float* __restrict__ b1) {
    int w = (blockIdx.x * blockDim.x + threadIdx.x) >> 5;
    int lane = threadIdx.x & 31;
    if (w >= NN) return;
    int beg = g_rowptr[w], end = g_rowptr[w + 1];
    int head = lane >> 3;
    float ald = g_ald1[w * 4 + head];
    float4 acc = make_float4(0.f, 0.f, 0.f, 0.f);
    float denom = 0.f;
    int e = beg;
    for (; e + 2 <= end; e += 2) {
        int s0 = g_ssrc[e], s1 = g_ssrc[e + 1];
        float p0 = __expf(lrelu(g_als1[s0 * 4 + head] + ald));
        float p1 = __expf(lrelu(g_als1[s1 * 4 + head] + ald));
        float4 v0 = *(const float4*)(g_h1 + (size_t)s0 * 128 + lane * 4);
        float4 v1 = *(const float4*)(g_h1 + (size_t)s1 * 128 + lane * 4);
        denom += p0 + p1;
        acc.x += p0 * v0.x + p1 * v1.x;
        acc.y += p0 * v0.y + p1 * v1.y;
        acc.z += p0 * v0.z + p1 * v1.z;
        acc.w += p0 * v0.w + p1 * v1.w;
    }
    if (e < end) {
        int s0 = g_ssrc[e];
        float p0 = __expf(lrelu(g_als1[s0 * 4 + head] + ald));
        float4 v0 = *(const float4*)(g_h1 + (size_t)s0 * 128 + lane * 4);
        denom += p0;
        acc.x += p0 * v0.x; acc.y += p0 * v0.y;
        acc.z += p0 * v0.z; acc.w += p0 * v0.w;
    }
    float inv = 1.f / fmaxf(denom, 1e-16f);
    float4 bias = *(const float4*)(b1 + lane * 4);
    acc.x = acc.x * inv + bias.x;
    acc.y = acc.y * inv + bias.y;
    acc.z = acc.z * inv + bias.z;
    acc.w = acc.w * inv + bias.w;
    *(float4*)(g_out1 + (size_t)w * 128 + lane * 4) = acc;
}

// ---------------- GEMM2 (tf32 tensor cores, ELU fused): h2 = elu(out1) @ W2 --
// 256 thr (8 warps); warp = 16 rows x 32 cols; W2 fully staged in smem.
__global__ __launch_bounds__(256) void k_gemm2(const float* __restrict__ W) {
    __shared__ uint32_t Ws[128 * 40];    // [k][n], stride 40 (=8 mod 32)
    int tid  = threadIdx.x;
    int w    = tid >> 5;
    int lane = tid & 31;
    int g    = lane >> 2;
    int t    = lane & 3;
    int bm   = blockIdx.x * 128;

    // stage W2 (128x32) as tf32: 1024 float4, 256 threads -> 4 iters
    const float4* Wg = (const float4*)W;
#pragma unroll
    for (int r = 0; r < 4; r++) {
        int idx = tid + r * 256;          // float4 index; 8 per row
        int row = idx >> 3, cv = idx & 7;
        float4 wv = Wg[row * 8 + cv];
        uint4 tv = make_uint4(f2tf(wv.x), f2tf(wv.y), f2tf(wv.z), f2tf(wv.w));
        *(uint4*)(Ws + row * 40 + cv * 4) = tv;
    }
    __syncthreads();

    int row0 = bm + w * 16 + g;
    int row1 = row0 + 8;
    bool ok0 = row0 < NN, ok1 = row1 < NN;
    const float* xr0 = g_out1 + (size_t)(ok0 ? row0 : 0) * 128;
    const float* xr1 = g_out1 + (size_t)(ok1 ? row1 : 0) * 128;

    float acc[4][4];
#pragma unroll
    for (int n = 0; n < 4; n++)
#pragma unroll
        for (int j = 0; j < 4; j++) acc[n][j] = 0.f;

#pragma unroll
    for (int ks = 0; ks < 16; ks++) {
        int k0 = ks * 8;
        uint32_t a0 = ok0 ? f2tf(eluf(xr0[k0 + t]))     : 0u;
        uint32_t a2 = ok0 ? f2tf(eluf(xr0[k0 + t + 4])) : 0u;
        uint32_t a1 = ok1 ? f2tf(eluf(xr1[k0 + t]))     : 0u;
        uint32_t a3 = ok1 ? f2tf(eluf(xr1[k0 + t + 4])) : 0u;
#pragma unroll
        for (int n = 0; n < 4; n++) {
            uint32_t b0 = Ws[(k0 + t) * 40 + n * 8 + g];
            uint32_t b1 = Ws[(k0 + t + 4) * 40 + n * 8 + g];
            asm volatile(
                "mma.sync.aligned.m16n8k8.row.col.f32.tf32.tf32.f32 "
                "{%0,%1,%2,%3}, {%4,%5,%6,%7}, {%8,%9}, {%0,%1,%2,%3};"
                : "+f"(acc[n][0]), "+f"(acc[n][1]), "+f"(acc[n][2]), "+f"(acc[n][3])
                : "r"(a0), "r"(a1), "r"(a2), "r"(a3), "r"(b0), "r"(b1));
        }
    }
#pragma unroll
    for (int n = 0; n < 4; n++) {
        if (ok0) *(float2*)(g_h2 + (size_t)row0 * 32 + n * 8 + 2 * t) =
            make_float2(acc[n][0], acc[n][1]);
        if (ok1) *(float2*)(g_h2 + (size_t)row1 * 32 + n * 8 + 2 * t) =
            make_float2(acc[n][2], acc[n][3]);
    }
}

// ---------------- attention scalars layer2 ----------------------------------
__global__ void k_al2(const float* __restrict__ a_src, const float* __restrict__ a_dst) {
    int n = blockIdx.x * blockDim.x + threadIdx.x;
    if (n >= NN) return;
    const float* hp = g_h2 + (size_t)n * 32;
    float s = 0.f, d = 0.f;
#pragma unroll
    for (int j = 0; j < 8; j++) {
        float4 v  = *(const float4*)(hp + j * 4);
        float4 as = *(const float4*)(a_src + j * 4);
        float4 ad = *(const float4*)(a_dst + j * 4);
        s += v.x * as.x + v.y * as.y + v.z * as.z + v.w * as.w;
        d += v.x * ad.x + v.y * ad.y + v.z * ad.z + v.w * ad.w;
    }
    g_als2[n] = s;
    g_ald2[n] = d;
}

// ---------------- layer2 fused softmax+aggregate: warp per node --------------
__global__ void k_fagg2(const float* __restrict__ b2, float* __restrict__ out) {
    int w = (blockIdx.x * blockDim.x + threadIdx.x) >> 5;
    int lane = threadIdx.x & 31;
    if (w >= NN) return;
    int beg = g_rowptr[w], end = g_rowptr[w + 1];
    float ald = g_ald2[w];
    float acc = 0.f, denom = 0.f;
    int e = beg;
    for (; e + 2 <= end; e += 2) {
        int s0 = g_ssrc[e], s1 = g_ssrc[e + 1];
        float p0 = __expf(lrelu(g_als2[s0] + ald));
        float p1 = __expf(lrelu(g_als2[s1] + ald));
        float v0 = g_h2[(size_t)s0 * 32 + lane];
        float v1 = g_h2[(size_t)s1 * 32 + lane];
        denom += p0 + p1;
        acc += p0 * v0 + p1 * v1;
    }
    if (e < end) {
        int s0 = g_ssrc[e];
        float p0 = __expf(lrelu(g_als2[s0] + ald));
        denom += p0;
        acc += p0 * g_h2[(size_t)s0 * 32 + lane];
    }
    out[(size_t)w * 32 + lane] = acc / fmaxf(denom, 1e-16f) + b2[lane];
}

// ---------------- launcher ---------------------------------------------------
extern "C" void kernel_launch(void* const* d_in, const int* in_sizes, int n_in,
                              void* d_out, int out_size) {
    const float* x      = (const float*)d_in[0];
    const float* W1     = (const float*)d_in[1];
    const float* a_src1 = (const float*)d_in[2];
    const float* a_dst1 = (const float*)d_in[3];
    const float* b1     = (const float*)d_in[4];
    const float* W2     = (const float*)d_in[5];
    const float* a_src2 = (const float*)d_in[6];
    const float* a_dst2 = (const float*)d_in[7];
    const float* b2     = (const float*)d_in[8];
    const void*  ei     = (const void*)d_in[9];
    float* out = (float*)d_out;

    k_detect <<<1, 256>>>((const int*)ei);
    k_zero   <<<NB, 256>>>();
    k_decode <<<(ETOT + 255) / 256, 256>>>(ei);
    k_scanA  <<<NB, 256>>>();
    k_scanB  <<<1, 256>>>();
    k_scanC  <<<NB, 256>>>();
    k_scatter<<<(ETOT + 255) / 256, 256>>>();
    k_gemm1  <<<(NN + 127) / 128, 256>>>(x, W1);
    k_al1    <<<(NN * H + 255) / 256, 256>>>(a_src1, a_dst1);
    k_fagg1  <<<(NN * 32 + 255) / 256, 256>>>(b1);
    k_gemm2  <<<(NN + 127) / 128, 256>>>(W2);
    k_al2    <<<(NN + 255) / 256, 256>>>(a_src2, a_dst2);
    k_fagg2  <<<(NN * 32 + 255) / 256, 256>>>(b2, out);
}

// round 10
// speedup vs baseline: 1.7309x; 1.0724x over previous
#include <cuda_runtime.h>
#include <cuda_fp16.h>
#include <cstdint>

#define NN   50000
#define EE   800000
#define ETOT 850000   // E + N self loops
#define F1   128      // HEADS*HID
#define H    4
#define FOUT 32
#define NB   196      // ceil(NN/256)

// ---------------- scratch (device globals; no allocations allowed) ----------
__device__ __align__(16) __half g_h1h[NN * F1];   // layer1 features (fp16)
__device__ __align__(16) float  g_out1[NN * F1];  // layer1 aggregate (fp32)
__device__ __align__(16) float  g_als1[NN * H];
__device__ __align__(16) float  g_ald1[NN * H];
__device__ __align__(16) __half g_h2h[NN * FOUT]; // layer2 features (fp16)
__device__ __align__(16) float  g_als2[NN];
__device__ __align__(16) float  g_ald2[NN];
__device__ int g_src[ETOT];
__device__ int g_dst[ETOT];
__device__ int g_cnt[NN];
__device__ int g_cursor[NN];
__device__ int g_rowptr[NN + 1];
__device__ int g_ssrc[ETOT];
__device__ int g_bsum[NB];
__device__ int g_boff[NB];
__device__ int g_is64;

// ---------------- helpers ---------------------------------------------------
__device__ __forceinline__ float lrelu(float v) { return v > 0.f ? v : 0.2f * v; }
__device__ __forceinline__ uint32_t f2tf(float f) {
    uint32_t u; asm("cvt.rna.tf32.f32 %0, %1;" : "=r"(u) : "f"(f)); return u;
}
__device__ __forceinline__ float eluf(float v) {
    return v > 0.f ? v : __expf(v) - 1.f;
}

// ---------------- edge dtype detection ---------------------------------------
__global__ void k_detect(const int* __restrict__ ei32) {
    __shared__ int any_nonzero;
    if (threadIdx.x == 0) any_nonzero = 0;
    __syncthreads();
    if (ei32[2 * (threadIdx.x * 1237) + 1] != 0) atomicOr(&any_nonzero, 1);
    __syncthreads();
    if (threadIdx.x == 0) g_is64 = any_nonzero ? 0 : 1;
}

__global__ void k_zero() {
    int i = blockIdx.x * blockDim.x + threadIdx.x;
    if (i < NN) g_cnt[i] = 0;
}

// decode + histogram fused
__global__ void k_decode(const void* __restrict__ ei) {
    int i = blockIdx.x * blockDim.x + threadIdx.x;
    if (i >= ETOT) return;
    int s, d;
    if (i >= EE) {
        s = d = i - EE;
    } else if (g_is64) {
        const long long* p = (const long long*)ei;
        s = (int)p[i]; d = (int)p[EE + i];
    } else {
        const int* q = (const int*)ei;
        s = q[i]; d = q[EE + i];
    }
    if ((unsigned)s >= NN) s = 0;
    if ((unsigned)d >= NN) d = 0;
    g_src[i] = s;
    g_dst[i] = d;
    atomicAdd(&g_cnt[d], 1);
}

// ---------------- parallel 3-stage exclusive scan of g_cnt -------------------
__global__ void k_scanA() {
    int b = blockIdx.x, tid = threadIdx.x;
    int i = b * 256 + tid;
    int c = (i < NN) ? g_cnt[i] : 0;
    int lane = tid & 31, wid = tid >> 5;
#pragma unroll
    for (int off = 16; off; off >>= 1) c += __shfl_down_sync(0xffffffffu, c, off);
    __shared__ int ws[8];
    if (lane == 0) ws[wid] = c;
    __syncthreads();
    if (tid == 0) {
        int s = 0;
#pragma unroll
        for (int j = 0; j < 8; j++) s += ws[j];
        g_bsum[b] = s;
    }
}

__global__ void k_scanB() {   // 1 block, 256 threads
    int tid = threadIdx.x;
    __shared__ int sh[256];
    int v = (tid < NB) ? g_bsum[tid] : 0;
    sh[tid] = v;
    __syncthreads();
    for (int off = 1; off < 256; off <<= 1) {
        int n = (tid >= off) ? sh[tid - off] : 0;
        __syncthreads();
        sh[tid] += n;
        __syncthreads();
    }
    if (tid < NB) g_boff[tid] = sh[tid] - v;   // exclusive
}

__global__ void k_scanC() {
    int b = blockIdx.x, tid = threadIdx.x;
    int i = b * 256 + tid;
    int c = (i < NN) ? g_cnt[i] : 0;
    int lane = tid & 31, wid = tid >> 5;
    int v = c;
#pragma unroll
    for (int off = 1; off < 32; off <<= 1) {
        int n = __shfl_up_sync(0xffffffffu, v, off);
        if (lane >= off) v += n;
    }
    __shared__ int ws[8];
    if (lane == 31) ws[wid] = v;
    __syncthreads();
    if (wid == 0) {
        int s = (lane < 8) ? ws[lane] : 0;
#pragma unroll
        for (int off = 1; off < 8; off <<= 1) {
            int n = __shfl_up_sync(0xffffffffu, s, off);
            if (lane >= off) s += n;
        }
        if (lane < 8) ws[lane] = s;
    }
    __syncthreads();
    int excl = v - c + (wid ? ws[wid - 1] : 0) + g_boff[b];
    if (i < NN) { g_rowptr[i] = excl; g_cursor[i] = excl; }
    if (i == 0) g_rowptr[NN] = ETOT;
}

__global__ void k_scatter() {
    int i = blockIdx.x * blockDim.x + threadIdx.x;
    if (i >= ETOT) return;
    int d = g_dst[i];
    int pos = atomicAdd(&g_cursor[d], 1);
    g_ssrc[pos] = g_src[i];
}

// ---------------- GEMM1 (tf32 tensor cores): h1 = x @ W1, fp16 out -----------
__global__ __launch_bounds__(256) void k_gemm1(const float* __restrict__ x,
                                               const float* __restrict__ W) {
    __shared__ uint32_t Ws[16 * 136];
    int tid  = threadIdx.x;
    int w    = tid >> 5;
    int lane = tid & 31;
    int g    = lane >> 2;
    int t    = lane & 3;
    int bm   = blockIdx.x * 128;

    int row0 = bm + w * 16 + g;
    int row1 = row0 + 8;
    bool ok0 = row0 < NN, ok1 = row1 < NN;
    const float* xr0 = x + (size_t)(ok0 ? row0 : 0) * 128;
    const float* xr1 = x + (size_t)(ok1 ? row1 : 0) * 128;

    float acc[16][4];
#pragma unroll
    for (int n = 0; n < 16; n++)
#pragma unroll
        for (int j = 0; j < 4; j++) acc[n][j] = 0.f;

    for (int chunk = 0; chunk < 8; chunk++) {
        const float4* Wg = (const float4*)(W + chunk * 16 * 128);
#pragma unroll
        for (int r = 0; r < 2; r++) {
            int idx = tid + r * 256;
            int row = idx >> 5, cv = idx & 31;
            float4 wv = Wg[row * 32 + cv];
            uint4 tv = make_uint4(f2tf(wv.x), f2tf(wv.y), f2tf(wv.z), f2tf(wv.w));
            *(uint4*)(Ws + row * 136 + cv * 4) = tv;
        }
        __syncthreads();
#pragma unroll
        for (int ks = 0; ks < 2; ks++) {
            int k0 = chunk * 16 + ks * 8;
            int kk = ks * 8;
            uint32_t a0 = ok0 ? f2tf(xr0[k0 + t])     : 0u;
            uint32_t a2 = ok0 ? f2tf(xr0[k0 + t + 4]) : 0u;
            uint32_t a1 = ok1 ? f2tf(xr1[k0 + t])     : 0u;
            uint32_t a3 = ok1 ? f2tf(xr1[k0 + t + 4]) : 0u;
#pragma unroll
            for (int n = 0; n < 16; n++) {
                uint32_t b0 = Ws[(kk + t) * 136 + n * 8 + g];
                uint32_t b1 = Ws[(kk + t + 4) * 136 + n * 8 + g];
                asm volatile(
                    "mma.sync.aligned.m16n8k8.row.col.f32.tf32.tf32.f32 "
                    "{%0,%1,%2,%3}, {%4,%5,%6,%7}, {%8,%9}, {%0,%1,%2,%3};"
                    : "+f"(acc[n][0]), "+f"(acc[n][1]), "+f"(acc[n][2]), "+f"(acc[n][3])
                    : "r"(a0), "r"(a1), "r"(a2), "r"(a3), "r"(b0), "r"(b1));
            }
        }
        __syncthreads();
    }
#pragma unroll
    for (int n = 0; n < 16; n++) {
        if (ok0) *(__half2*)(g_h1h + (size_t)row0 * 128 + n * 8 + 2 * t) =
            __floats2half2_rn(acc[n][0], acc[n][1]);
        if (ok1) *(__half2*)(g_h1h + (size_t)row1 * 128 + n * 8 + 2 * t) =
            __floats2half2_rn(acc[n][2], acc[n][3]);
    }
}

// ---------------- attention scalars layer1 (fp16 h1) -------------------------
__global__ void k_al1(const float* __restrict__ a_src, const float* __restrict__ a_dst) {
    int i = blockIdx.x * blockDim.x + threadIdx.x;
    if (i >= NN * H) return;
    int n = i >> 2, h = i & 3;
    const __half2* hp = (const __half2*)(g_h1h + (size_t)n * 128 + h * 32);
    float s = 0.f, d = 0.f;
#pragma unroll
    for (int j = 0; j < 16; j++) {
        float2 v = __half22float2(hp[j]);
        float as0 = a_src[h * 32 + 2 * j], as1 = a_src[h * 32 + 2 * j + 1];
        float ad0 = a_dst[h * 32 + 2 * j], ad1 = a_dst[h * 32 + 2 * j + 1];
        s += v.x * as0 + v.y * as1;
        d += v.x * ad0 + v.y * ad1;
    }
    g_als1[i] = s;
    g_ald1[i] = d;
}

// ---------------- layer1 fused softmax+aggregate: warp per node --------------
__global__ void k_fagg1(const float* __restrict__ b1) {
    int w = (blockIdx.x * blockDim.x + threadIdx.x) >> 5;
    int lane = threadIdx.x & 31;
    if (w >= NN) return;
    int beg = g_rowptr[w], end = g_rowptr[w + 1];
    int head = lane >> 3;
    float ald = g_ald1[w * 4 + head];
    float4 acc = make_float4(0.f, 0.f, 0.f, 0.f);
    float denom = 0.f;
    int e = beg;
    for (; e + 2 <= end; e += 2) {
        int s0 = g_ssrc[e], s1 = g_ssrc[e + 1];
        float p0 = __expf(lrelu(g_als1[s0 * 4 + head] + ald));
        float p1 = __expf(lrelu(g_als1[s1 * 4 + head] + ald));
        const __half2* h0 = (const __half2*)(g_h1h + (size_t)s0 * 128) + lane * 2;
        const __half2* h1 = (const __half2*)(g_h1h + (size_t)s1 * 128) + lane * 2;
        float2 a0 = __half22float2(h0[0]), b0v = __half22float2(h0[1]);
        float2 a1 = __half22float2(h1[0]), b1v = __half22float2(h1[1]);
        denom += p0 + p1;
        acc.x += p0 * a0.x + p1 * a1.x;
        acc.y += p0 * a0.y + p1 * a1.y;
        acc.z += p0 * b0v.x + p1 * b1v.x;
        acc.w += p0 * b0v.y + p1 * b1v.y;
    }
    if (e < end) {
        int s0 = g_ssrc[e];
        float p0 = __expf(lrelu(g_als1[s0 * 4 + head] + ald));
        const __half2* h0 = (const __half2*)(g_h1h + (size_t)s0 * 128) + lane * 2;
        float2 a0 = __half22float2(h0[0]), b0v = __half22float2(h0[1]);
        denom += p0;
        acc.x += p0 * a0.x; acc.y += p0 * a0.y;
        acc.z += p0 * b0v.x; acc.w += p0 * b0v.y;
    }
    float inv = 1.f / fmaxf(denom, 1e-16f);
    float4 bias = *(const float4*)(b1 + lane * 4);
    acc.x = acc.x * inv + bias.x;
    acc.y = acc.y * inv + bias.y;
    acc.z = acc.z * inv + bias.z;
    acc.w = acc.w * inv + bias.w;
    *(float4*)(g_out1 + (size_t)w * 128 + lane * 4) = acc;
}

// ---------------- GEMM2 (tf32, ELU fused): h2 = elu(out1) @ W2, fp16 out -----
__global__ __launch_bounds__(256) void k_gemm2(const float* __restrict__ W) {
    __shared__ uint32_t Ws[128 * 40];
    int tid  = threadIdx.x;
    int w    = tid >> 5;
    int lane = tid & 31;
    int g    = lane >> 2;
    int t    = lane & 3;
    int bm   = blockIdx.x * 128;

    const float4* Wg = (const float4*)W;
#pragma unroll
    for (int r = 0; r < 4; r++) {
        int idx = tid + r * 256;
        int row = idx >> 3, cv = idx & 7;
        float4 wv = Wg[row * 8 + cv];
        uint4 tv = make_uint4(f2tf(wv.x), f2tf(wv.y), f2tf(wv.z), f2tf(wv.w));
        *(uint4*)(Ws + row * 40 + cv * 4) = tv;
    }
    __syncthreads();

    int row0 = bm + w * 16 + g;
    int row1 = row0 + 8;
    bool ok0 = row0 < NN, ok1 = row1 < NN;
    const float* xr0 = g_out1 + (size_t)(ok0 ? row0 : 0) * 128;
    const float* xr1 = g_out1 + (size_t)(ok1 ? row1 : 0) * 128;

    float acc[4][4];
#pragma unroll
    for (int n = 0; n < 4; n++)
#pragma unroll
        for (int j = 0; j < 4; j++) acc[n][j] = 0.f;

#pragma unroll
    for (int ks = 0; ks < 16; ks++) {
        int k0 = ks * 8;
        uint32_t a0 = ok0 ? f2tf(eluf(xr0[k0 + t]))     : 0u;
        uint32_t a2 = ok0 ? f2tf(eluf(xr0[k0 + t + 4])) : 0u;
        uint32_t a1 = ok1 ? f2tf(eluf(xr1[k0 + t]))     : 0u;
        uint32_t a3 = ok1 ? f2tf(eluf(xr1[k0 + t + 4])) : 0u;
#pragma unroll
        for (int n = 0; n < 4; n++) {
            uint32_t b0 = Ws[(k0 + t) * 40 + n * 8 + g];
            uint32_t b1 = Ws[(k0 + t + 4) * 40 + n * 8 + g];
            asm volatile(
                "mma.sync.aligned.m16n8k8.row.col.f32.tf32.tf32.f32 "
                "{%0,%1,%2,%3}, {%4,%5,%6,%7}, {%8,%9}, {%0,%1,%2,%3};"
                : "+f"(acc[n][0]), "+f"(acc[n][1]), "+f"(acc[n][2]), "+f"(acc[n][3])
                : "r"(a0), "r"(a1), "r"(a2), "r"(a3), "r"(b0), "r"(b1));
        }
    }
#pragma unroll
    for (int n = 0; n < 4; n++) {
        if (ok0) *(__half2*)(g_h2h + (size_t)row0 * 32 + n * 8 + 2 * t) =
            __floats2half2_rn(acc[n][0], acc[n][1]);
        if (ok1) *(__half2*)(g_h2h + (size_t)row1 * 32 + n * 8 + 2 * t) =
            __floats2half2_rn(acc[n][2], acc[n][3]);
    }
}

// ---------------- attention scalars layer2 (fp16 h2) -------------------------
__global__ void k_al2(const float* __restrict__ a_src, const float* __restrict__ a_dst) {
    int n = blockIdx.x * blockDim.x + threadIdx.x;
    if (n >= NN) return;
    const __half2* hp = (const __half2*)(g_h2h + (size_t)n * 32);
    float s = 0.f, d = 0.f;
#pragma unroll
    for (int j = 0; j < 16; j++) {
        float2 v = __half22float2(hp[j]);
        s += v.x * a_src[2 * j] + v.y * a_src[2 * j + 1];
        d += v.x * a_dst[2 * j] + v.y * a_dst[2 * j + 1];
    }
    g_als2[n] = s;
    g_ald2[n] = d;
}

// ---------------- layer2 fused softmax+aggregate: warp per node --------------
__global__ void k_fagg2(const float* __restrict__ b2, float* __restrict__ out) {
    int w = (blockIdx.x * blockDim.x + threadIdx.x) >> 5;
    int lane = threadIdx.x & 31;
    if (w >= NN) return;
    int beg = g_rowptr[w], end = g_rowptr[w + 1];
    float ald = g_ald2[w];
    float acc = 0.f, denom = 0.f;
    int e = beg;
    for (; e + 2 <= end; e += 2) {
        int s0 = g_ssrc[e], s1 = g_ssrc[e + 1];
        float p0 = __expf(lrelu(g_als2[s0] + ald));
        float p1 = __expf(lrelu(g_als2[s1] + ald));
        float v0 = __half2float(g_h2h[(size_t)s0 * 32 + lane]);
        float v1 = __half2float(g_h2h[(size_t)s1 * 32 + lane]);
        denom += p0 + p1;
        acc += p0 * v0 + p1 * v1;
    }
    if (e < end) {
        int s0 = g_ssrc[e];
        float p0 = __expf(lrelu(g_als2[s0] + ald));
        denom += p0;
        acc += p0 * __half2float(g_h2h[(size_t)s0 * 32 + lane]);
    }
    out[(size_t)w * 32 + lane] = acc / fmaxf(denom, 1e-16f) + b2[lane];
}

// ---------------- launcher ---------------------------------------------------
extern "C" void kernel_launch(void* const* d_in, const int* in_sizes, int n_in,
                              void* d_out, int out_size) {
    const float* x      = (const float*)d_in[0];
    const float* W1     = (const float*)d_in[1];
    const float* a_src1 = (const float*)d_in[2];
    const float* a_dst1 = (const float*)d_in[3];
    const float* b1     = (const float*)d_in[4];
    const float* W2     = (const float*)d_in[5];
    const float* a_src2 = (const float*)d_in[6];
    const float* a_dst2 = (const float*)d_in[7];
    const float* b2     = (const float*)d_in[8];
    const void*  ei     = (const void*)d_in[9];
    float* out = (float*)d_out;

    k_detect <<<1, 256>>>((const int*)ei);
    k_zero   <<<NB, 256>>>();
    k_decode <<<(ETOT + 255) / 256, 256>>>(ei);
    k_scanA  <<<NB, 256>>>();
    k_scanB  <<<1, 256>>>();
    k_scanC  <<<NB, 256>>>();
    k_scatter<<<(ETOT + 255) / 256, 256>>>();
    k_gemm1  <<<(NN + 127) / 128, 256>>>(x, W1);
    k_al1    <<<(NN * H + 255) / 256, 256>>>(a_src1, a_dst1);
    k_fagg1  <<<(NN * 32 + 255) / 256, 256>>>(b1);
    k_gemm2  <<<(NN + 127) / 128, 256>>>(W2);
    k_al2    <<<(NN + 255) / 256, 256>>>(a_src2, a_dst2);
    k_fagg2  <<<(NN * 32 + 255) / 256, 256>>>(b2, out);
}